// round 17
// baseline (speedup 1.0000x reference)
#include <cuda_runtime.h>
#include <cuda_fp16.h>
#include <mma.h>
#include <cstdint>

using namespace nvcuda;

// Problem constants
#define BB 2
#define SS 2048
#define DD 1024
#define HH 16
#define DK 64
#define MT (BB*SS)      // 4096 token rows

// Scratch (device globals — no allocation allowed)
__device__ __half g_Xh[3*MT*DD];        // fp16 q,k,v inputs
__device__ __half g_Wh[4*DD*DD];        // fp16 weights
__device__ __half g_Qh[BB*HH*SS*DK];    // [B,H,S,DK]
__device__ __half g_Kh[BB*HH*SS*DK];
__device__ __half g_Vt[BB*HH*DK*SS];    // [B,H,DK,S] transposed V (written by GEMM)
__device__ __half g_Ctx[BB*SS*DD];      // [B,S,D]

// ---------------------------------------------------------------------------
// helpers
// ---------------------------------------------------------------------------
__device__ __forceinline__ uint32_t smem_u32(const void* p) {
    uint32_t a;
    asm("{ .reg .u64 t; cvta.to.shared.u64 t, %1; cvt.u32.u64 %0, t; }"
        : "=r"(a) : "l"(p));
    return a;
}

__device__ __forceinline__ void mma16816(float c[4], const uint32_t a[4],
                                         uint32_t b0, uint32_t b1) {
    asm volatile(
        "mma.sync.aligned.m16n8k16.row.col.f32.f16.f16.f32 "
        "{%0,%1,%2,%3}, {%4,%5,%6,%7}, {%8,%9}, {%0,%1,%2,%3};"
        : "+f"(c[0]), "+f"(c[1]), "+f"(c[2]), "+f"(c[3])
        : "r"(a[0]), "r"(a[1]), "r"(a[2]), "r"(a[3]), "r"(b0), "r"(b1));
}

#define CP_ASYNC16(saddr, gptr) \
    asm volatile("cp.async.cg.shared.global [%0], [%1], 16;" \
                 :: "r"((uint32_t)(saddr)), "l"(gptr))
#define CP_COMMIT() asm volatile("cp.async.commit_group;" ::: "memory")
#define CP_WAIT(n)  asm volatile("cp.async.wait_group %0;" :: "n"(n) : "memory")

// ---------------------------------------------------------------------------
// Pre-pass: convert all 7 fp32 tensors to fp16 in ONE launch.
// ---------------------------------------------------------------------------
__global__ void prep_all(const float* __restrict__ q, const float* __restrict__ k,
                         const float* __restrict__ v,
                         const float* __restrict__ w0, const float* __restrict__ w1,
                         const float* __restrict__ w2, const float* __restrict__ w3,
                         __half* __restrict__ Xh, __half* __restrict__ Wh)
{
    const int z = blockIdx.z;
    const float* src;
    __half* d;
    if (z < 3) {
        src = (z == 0) ? q : (z == 1) ? k : v;
        d = Xh + (size_t)z * MT * DD;
    } else {
        if (blockIdx.x >= (DD*DD)/(4*256)) return;
        src = (z == 3) ? w0 : (z == 4) ? w1 : (z == 5) ? w2 : w3;
        d = Wh + (size_t)(z - 3) * DD * DD;
    }
    int i = blockIdx.x * 256 + threadIdx.x;
    float4 vv = *(const float4*)&src[(size_t)i * 4];
    *(__half2*)&d[(size_t)i*4 + 0] = __floats2half2_rn(vv.x, vv.y);
    *(__half2*)&d[(size_t)i*4 + 2] = __floats2half2_rn(vv.z, vv.w);
}

// ---------------------------------------------------------------------------
// wmma fp16 GEMM body, 3-stage cp.async pipeline, ONE sync per k-stage.
// C[4096,1024] = A @ W + bias. 128x128 CTA tile, BK=32, 8 warps.
// MODE 0: fp32 row-major.  MODE 1: fp16 head-split [B,H,S,DK].
// MODE 2: fp16 transposed head-split [B,H,DK,S]  (V path).
// ---------------------------------------------------------------------------
#define GBK 32
#define ALD 40    // A smem row stride (halfs)
#define BLD 136   // B smem row stride (halfs)
#define GA_STAGE (128*ALD)                       // 5120 halfs
#define GB_STAGE (GBK*BLD)                       // 4352 halfs
#define GSTAGE   (GA_STAGE + GB_STAGE)           // 9472 halfs
#define GNSTG 3
#define GSMEM_B  (GNSTG*GSTAGE*2)                // 56832 bytes

template<int MODE>
__device__ __forceinline__ void gemm_body(
    const __half* __restrict__ A, const __half* __restrict__ B,
    const float* __restrict__ bias, void* __restrict__ C)
{
    extern __shared__ __align__(128) __half smh[];
    float* smf = (float*)smh;              // epilogue staging (64x136 fp32)
    const uint32_t sbase = smem_u32(smh);

    const int tid = threadIdx.x;
    const int w  = tid >> 5;
    const int wr = w >> 1;            // 0..3 -> rows 32*wr
    const int wc = w & 1;             // 0..1 -> cols 64*wc
    const int row0 = blockIdx.y * 128;
    const int col0 = blockIdx.x * 128;

    wmma::fragment<wmma::accumulator, 16, 16, 16, float> acc[2][4];
    #pragma unroll
    for (int i = 0; i < 2; i++)
        #pragma unroll
        for (int j = 0; j < 4; j++) wmma::fill_fragment(acc[i][j], 0.f);

    auto load_stage = [&](int ks, int slot) {
        const __half* Ag = A + (size_t)row0 * DD + ks * GBK;
        const __half* Bg = B + (size_t)(ks * GBK) * DD + col0;
        const uint32_t dA = sbase + slot * GSTAGE * 2;
        const uint32_t dB = dA + GA_STAGE * 2;
        #pragma unroll
        for (int u = 0; u < 2; u++) {
            int c = u * 256 + tid;             // A: 512 chunks of 8 halfs
            int r = c >> 2, ch = c & 3;
            CP_ASYNC16(dA + r * (ALD*2) + ch * 16, Ag + (size_t)r * DD + ch * 8);
        }
        #pragma unroll
        for (int u = 0; u < 2; u++) {
            int c = u * 256 + tid;             // B: 512 chunks
            int r = c >> 4, ch = c & 15;
            CP_ASYNC16(dB + r * (BLD*2) + ch * 16, Bg + (size_t)r * DD + ch * 8);
        }
        CP_COMMIT();
    };

    load_stage(0, 0);
    load_stage(1, 1);

    const int NK = DD / GBK;          // 32
    int slot = 0;
    for (int ks = 0; ks < NK; ks++) {
        if (ks == NK - 1) { CP_WAIT(0); } else { CP_WAIT(1); }
        __syncthreads();              // single barrier per stage
        if (ks + 2 < NK) load_stage(ks + 2, (slot + 2) % GNSTG);

        const __half* Ab = smh + slot * GSTAGE + wr * 32 * ALD;
        const __half* Bb = smh + slot * GSTAGE + GA_STAGE + wc * 64;
        #pragma unroll
        for (int kk = 0; kk < 2; kk++) {      // BK/16
            wmma::fragment<wmma::matrix_a, 16, 16, 16, __half, wmma::row_major> fa[2];
            wmma::fragment<wmma::matrix_b, 16, 16, 16, __half, wmma::row_major> fb[4];
            #pragma unroll
            for (int im = 0; im < 2; im++)
                wmma::load_matrix_sync(fa[im], Ab + im * 16 * ALD + kk * 16, ALD);
            #pragma unroll
            for (int in = 0; in < 4; in++)
                wmma::load_matrix_sync(fb[in], Bb + kk * 16 * BLD + in * 16, BLD);
            #pragma unroll
            for (int im = 0; im < 2; im++)
                #pragma unroll
                for (int in = 0; in < 4; in++)
                    wmma::mma_sync(acc[im][in], fa[im], fb[in], acc[im][in]);
        }
        slot = (slot + 1) % GNSTG;
        // no trailing sync: 3-stage ring => writer is 2 stages ahead of reader,
        // and the next iteration's barrier orders all warps past compute(ks).
    }
    __syncthreads();                  // mainloop done; smem becomes epilogue staging

    // Epilogue: two passes of 64 rows through fp32 smem staging (ld=136)
    #pragma unroll
    for (int p = 0; p < 2; p++) {
        if (wr >= p * 2 && wr < p * 2 + 2) {
            const int lr = (wr - p * 2) * 32;
            #pragma unroll
            for (int im = 0; im < 2; im++)
                #pragma unroll
                for (int in = 0; in < 4; in++)
                    wmma::store_matrix_sync(&smf[(lr + im*16) * 136 + wc*64 + in*16],
                                            acc[im][in], 136, wmma::mem_row_major);
        }
        __syncthreads();

        if (MODE == 2) {
            // V: write transposed [B,H,DK,S], coalesced along s.
            const int b  = row0 >> 11;
            const int s0 = (row0 & (SS - 1)) + p * 64;
            #pragma unroll
            for (int u = 0; u < 4; u++) {
                int id  = u * 256 + tid;            // 1024: col(128) x strip(8)
                int col = id >> 3;
                int r   = (id & 7) * 8;
                const int gcol = col0 + col;
                const int h  = gcol >> 6;
                const int dk = gcol & (DK - 1);
                const float bb = bias[gcol];
                __half hv[8];
                #pragma unroll
                for (int j = 0; j < 8; j++)
                    hv[j] = __float2half_rn(smf[(r + j) * 136 + col] + bb);
                __half* dst = (__half*)C + (((size_t)(b*HH + h))*DK + dk)*SS + s0 + r;
                *(uint4*)dst = *(uint4*)hv;
            }
        } else {
            #pragma unroll
            for (int u = 0; u < 8; u++) {
                int id = u * 256 + tid;                 // 2048 float4s
                int r  = id >> 5;
                int c4 = (id & 31) * 4;
                float4 vv = *(const float4*)&smf[r * 136 + c4];
                const int col = col0 + c4;
                vv.x += bias[col];   vv.y += bias[col+1];
                vv.z += bias[col+2]; vv.w += bias[col+3];
                const int trow = row0 + p * 64 + r;
                if (MODE == 0) {
                    *(float4*)&((float*)C)[(size_t)trow * DD + col] = vv;
                } else {
                    const int b = trow >> 11;
                    const int s = trow & (SS - 1);
                    const int h = col >> 6;
                    const int dk = col & (DK - 1);
                    __half* dst = (__half*)C + (((size_t)(b*HH + h))*SS + s)*DK + dk;
                    *(__half2*)&dst[0] = __floats2half2_rn(vv.x, vv.y);
                    *(__half2*)&dst[2] = __floats2half2_rn(vv.z, vv.w);
                }
            }
        }
        __syncthreads();
    }
}

// Merged QKV projection: grid (8, 32, 3). V goes out pre-transposed.
__global__ void __launch_bounds__(256)
gemm_qkv(const __half* __restrict__ Xh, const __half* __restrict__ Wh,
         const float* __restrict__ bq, const float* __restrict__ bk,
         const float* __restrict__ bv,
         __half* __restrict__ Qh, __half* __restrict__ Kh, __half* __restrict__ Vt)
{
    const int z = blockIdx.z;
    const __half* A = Xh + (size_t)z * MT * DD;
    const __half* B = Wh + (size_t)z * DD * DD;
    if (z == 0)      gemm_body<1>(A, B, bq, Qh);
    else if (z == 1) gemm_body<1>(A, B, bk, Kh);
    else             gemm_body<2>(A, B, bv, Vt);
}

__global__ void __launch_bounds__(256)
gemm_out(const __half* __restrict__ Ctx, const __half* __restrict__ Wh,
         const float* __restrict__ bo, float* __restrict__ C)
{
    gemm_body<0>(Ctx, Wh, bo, C);
}

// ---------------------------------------------------------------------------
// Flash attention, fp16 mma m16n8k16, P fully register-resident.
// CTA = (bh, 128-query tile), 8 warps x 16 query rows.
// K [key][dk] and V^T [dk][key] fp16 smem, double-buffered cp.async.
// ---------------------------------------------------------------------------
#define HPAD 72
#define AT_KS   (2*64*HPAD)                // halfs, one operand double-buffered
#define AT_SMEM_B (2*AT_KS*2)              // K + V, bytes = 36864

__global__ void __launch_bounds__(256, 2)
attn_tc(const __half* __restrict__ Qh, const __half* __restrict__ Kh,
        const __half* __restrict__ Vt, __half* __restrict__ Ctx)
{
    extern __shared__ __align__(128) __half smh[];
    __half* Ks = smh;                       // [2][64][72]  (key-major)
    __half* Vs = smh + AT_KS;               // [2][64][72]  (dk-major: V^T)
    const uint32_t sKs = smem_u32(Ks);
    const uint32_t sVs = smem_u32(Vs);

    const int bh = blockIdx.x;
    const int qt = (gridDim.y - 1) - blockIdx.y;    // big tiles first
    const int b  = bh >> 4;
    const int h  = bh & (HH - 1);

    const int tid  = threadIdx.x;
    const int w    = tid >> 5;
    const int lane = tid & 31;
    const int g    = lane >> 2;
    const int t    = lane & 3;
    const int r0   = w * 16;

    const __half* Qp = Qh + (size_t)bh * SS * DK + (size_t)qt * 128 * DK;
    const __half* Kp = Kh + (size_t)bh * SS * DK;
    const __half* Vp = Vt + (size_t)bh * DK * SS;

    // Q fragments straight from global (fp16 pairs)
    uint32_t qf[4][4];
    #pragma unroll
    for (int ks = 0; ks < 4; ks++) {
        const int k0 = ks * 16;
        qf[ks][0] = *(const uint32_t*)&Qp[(size_t)(r0+g  )*DK + k0 + 2*t    ];
        qf[ks][1] = *(const uint32_t*)&Qp[(size_t)(r0+g+8)*DK + k0 + 2*t    ];
        qf[ks][2] = *(const uint32_t*)&Qp[(size_t)(r0+g  )*DK + k0 + 2*t + 8];
        qf[ks][3] = *(const uint32_t*)&Qp[(size_t)(r0+g+8)*DK + k0 + 2*t + 8];
    }

    float m0 = -1e30f, m1 = -1e30f, l0 = 0.f, l1 = 0.f;
    float Oa[8][4];
    #pragma unroll
    for (int f = 0; f < 8; f++)
        #pragma unroll
        for (int r = 0; r < 4; r++) Oa[f][r] = 0.f;

    const int ktmax = 2 * qt + 1;
    const float SCL = 0.125f * 1.44269504088896f;   // 1/sqrt(dk) * log2(e)

    // K tile [64 keys][64 dk], V^T tile [64 dk][64 keys]
    auto load_kv = [&](int kt, int buf) {
        const uint32_t dK = sKs + buf * (64*HPAD*2);
        const uint32_t dV = sVs + buf * (64*HPAD*2);
        #pragma unroll
        for (int u = 0; u < 2; u++) {
            int c = u * 256 + tid;            // 512 chunks each of 8 halfs
            int row = c >> 3, ch = c & 7;
            CP_ASYNC16(dK + row*(HPAD*2) + ch*16,
                       Kp + (size_t)(kt*64 + row)*DK + ch*8);
            CP_ASYNC16(dV + row*(HPAD*2) + ch*16,
                       Vp + (size_t)row*SS + kt*64 + ch*8);
        }
        CP_COMMIT();
    };

    load_kv(0, 0);

    for (int kt = 0; kt <= ktmax; kt++) {
        CP_WAIT(0);
        __syncthreads();      // load(kt) visible; all warps done with other buffer
        if (kt + 1 <= ktmax) load_kv(kt + 1, (kt + 1) & 1);

        const __half* Kb = Ks + (kt & 1) * 64 * HPAD;
        const __half* Vb = Vs + (kt & 1) * 64 * HPAD;

        // S = Q @ K^T
        float Sa[8][4];
        #pragma unroll
        for (int f = 0; f < 8; f++)
            #pragma unroll
            for (int r = 0; r < 4; r++) Sa[f][r] = 0.f;
        #pragma unroll
        for (int ks = 0; ks < 4; ks++) {
            const int k0 = ks * 16;
            #pragma unroll
            for (int f = 0; f < 8; f++) {
                uint32_t b0 = *(const uint32_t*)&Kb[(f*8+g)*HPAD + k0 + 2*t    ];
                uint32_t b1 = *(const uint32_t*)&Kb[(f*8+g)*HPAD + k0 + 2*t + 8];
                mma16816(Sa[f], qf[ks], b0, b1);
            }
        }
        #pragma unroll
        for (int f = 0; f < 8; f++) {
            Sa[f][0] *= SCL; Sa[f][1] *= SCL; Sa[f][2] *= SCL; Sa[f][3] *= SCL;
        }

        // causal mask (near/on diagonal only)
        if (kt >= 2 * qt) {
            const int grow0 = qt*128 + r0 + g;
            const int grow1 = grow0 + 8;
            #pragma unroll
            for (int f = 0; f < 8; f++) {
                const int c0 = kt*64 + f*8 + 2*t;
                if (c0     > grow0) Sa[f][0] = -1e30f;
                if (c0 + 1 > grow0) Sa[f][1] = -1e30f;
                if (c0     > grow1) Sa[f][2] = -1e30f;
                if (c0 + 1 > grow1) Sa[f][3] = -1e30f;
            }
        }

        // online softmax (log2 domain)
        float mx0 = -1e30f, mx1 = -1e30f;
        #pragma unroll
        for (int f = 0; f < 8; f++) {
            mx0 = fmaxf(mx0, fmaxf(Sa[f][0], Sa[f][1]));
            mx1 = fmaxf(mx1, fmaxf(Sa[f][2], Sa[f][3]));
        }
        mx0 = fmaxf(mx0, __shfl_xor_sync(0xffffffffu, mx0, 1));
        mx0 = fmaxf(mx0, __shfl_xor_sync(0xffffffffu, mx0, 2));
        mx1 = fmaxf(mx1, __shfl_xor_sync(0xffffffffu, mx1, 1));
        mx1 = fmaxf(mx1, __shfl_xor_sync(0xffffffffu, mx1, 2));

        const float mn0 = fmaxf(m0, mx0), mn1 = fmaxf(m1, mx1);
        const float corr0 = exp2f(m0 - mn0), corr1 = exp2f(m1 - mn1);
        float s0 = 0.f, s1 = 0.f;
        uint32_t phl[8], phh[8];     // P fragments in registers (rows g / g+8)
        #pragma unroll
        for (int f = 0; f < 8; f++) {
            float p00 = exp2f(Sa[f][0] - mn0);
            float p01 = exp2f(Sa[f][1] - mn0);
            float p10 = exp2f(Sa[f][2] - mn1);
            float p11 = exp2f(Sa[f][3] - mn1);
            s0 += p00 + p01;  s1 += p10 + p11;
            __half2 h0 = __floats2half2_rn(p00, p01);
            __half2 h1 = __floats2half2_rn(p10, p11);
            phl[f] = *(uint32_t*)&h0;
            phh[f] = *(uint32_t*)&h1;
        }
        s0 += __shfl_xor_sync(0xffffffffu, s0, 1);
        s0 += __shfl_xor_sync(0xffffffffu, s0, 2);
        s1 += __shfl_xor_sync(0xffffffffu, s1, 1);
        s1 += __shfl_xor_sync(0xffffffffu, s1, 2);
        l0 = l0 * corr0 + s0;  m0 = mn0;
        l1 = l1 * corr1 + s1;  m1 = mn1;

        #pragma unroll
        for (int f = 0; f < 8; f++) {
            Oa[f][0] *= corr0; Oa[f][1] *= corr0;
            Oa[f][2] *= corr1; Oa[f][3] *= corr1;
        }

        // O += P @ V   (A = P from registers, B = V^T [dk][key])
        #pragma unroll
        for (int ks = 0; ks < 4; ks++) {
            const int k0 = ks * 16;
            uint32_t pa[4];
            pa[0] = phl[2*ks];
            pa[1] = phh[2*ks];
            pa[2] = phl[2*ks + 1];
            pa[3] = phh[2*ks + 1];
            #pragma unroll
            for (int f = 0; f < 8; f++) {
                uint32_t b0 = *(const uint32_t*)&Vb[(f*8+g)*HPAD + k0 + 2*t    ];
                uint32_t b1 = *(const uint32_t*)&Vb[(f*8+g)*HPAD + k0 + 2*t + 8];
                mma16816(Oa[f], pa, b0, b1);
            }
        }
    }

    // normalize + write Ctx [B,S,D] fp16 (feeds final GEMM)
    const float inv0 = 1.f / l0, inv1 = 1.f / l1;
    const int srow0 = qt*128 + r0 + g;
    const int srow1 = srow0 + 8;
    #pragma unroll
    for (int f = 0; f < 8; f++) {
        const int col = h*64 + f*8 + 2*t;
        *(__half2*)&Ctx[((size_t)(b*SS + srow0))*DD + col] =
            __floats2half2_rn(Oa[f][0]*inv0, Oa[f][1]*inv0);
        *(__half2*)&Ctx[((size_t)(b*SS + srow1))*DD + col] =
            __floats2half2_rn(Oa[f][2]*inv1, Oa[f][3]*inv1);
    }
}

// ---------------------------------------------------------------------------
extern "C" void kernel_launch(void* const* d_in, const int* in_sizes, int n_in,
                              void* d_out, int out_size)
{
    const float* q  = (const float*)d_in[0];
    const float* k  = (const float*)d_in[1];
    const float* v  = (const float*)d_in[2];
    // d_in[3] = mask (strict causal tril) — implemented analytically
    const float* Wq = (const float*)d_in[4];
    const float* bq = (const float*)d_in[5];
    const float* Wk = (const float*)d_in[6];
    const float* bk = (const float*)d_in[7];
    const float* Wv = (const float*)d_in[8];
    const float* bv = (const float*)d_in[9];
    const float* Wo = (const float*)d_in[10];
    const float* bo = (const float*)d_in[11];
    float* out = (float*)d_out;

    __half *pXh, *pWh, *pQh, *pKh, *pVt, *pCtx;
    cudaGetSymbolAddress((void**)&pXh,  g_Xh);
    cudaGetSymbolAddress((void**)&pWh,  g_Wh);
    cudaGetSymbolAddress((void**)&pQh,  g_Qh);
    cudaGetSymbolAddress((void**)&pKh,  g_Kh);
    cudaGetSymbolAddress((void**)&pVt,  g_Vt);
    cudaGetSymbolAddress((void**)&pCtx, g_Ctx);

    cudaFuncSetAttribute(gemm_qkv, cudaFuncAttributeMaxDynamicSharedMemorySize, GSMEM_B);
    cudaFuncSetAttribute(gemm_out, cudaFuncAttributeMaxDynamicSharedMemorySize, GSMEM_B);
    cudaFuncSetAttribute(attn_tc,  cudaFuncAttributeMaxDynamicSharedMemorySize, AT_SMEM_B);

    // fp32 -> fp16 conversion (single launch)
    prep_all<<<dim3(MT*DD/(4*256), 1, 7), 256>>>(q, k, v, Wq, Wk, Wv, Wo, pXh, pWh);

    // merged QKV projection; V written pre-transposed
    gemm_qkv<<<dim3(DD/128, MT/128, 3), 256, GSMEM_B>>>(
        pXh, pWh, bq, bk, bv, pQh, pKh, pVt);

    dim3 gAttn(BB*HH, SS/128);    // (32, 16), qt reversed inside
    attn_tc<<<gAttn, 256, AT_SMEM_B>>>(pQh, pKh, pVt, pCtx);

    gemm_out<<<dim3(DD/128, MT/128), 256, GSMEM_B>>>(pCtx, pWh + 3*(size_t)DD*DD, bo, out);
}